// round 14
// baseline (speedup 1.0000x reference)
#include <cuda_runtime.h>
#include <cuda_bf16.h>
#include <math.h>

// out[b,t,f,c] = sum_{s<=t} w^{t-s} x[b,s,f] + mem[b,f,c] * w^{t+1},
// w = exp(clip(a[f]) + i*b[c])  ==> complex IIR  y[t] = w*y[t-1] + x[t], y[-1]=mem.
// Parallel-in-T: 8 chunks of 64; chunk sums compose via E_i = w^64 E_{i-1} + S_i.
// R13 (R4 + __ldcs/__stcs streaming hints) + single-wave residency:
// __launch_bounds__(256,7) -> 1036 resident blocks >= 1024 grid (no wave tail).
// w^64 computed after phase 1 to shrink live ranges (fit 36 regs).

#define B_DIM 8
#define T_DIM 512
#define F_DIM 1024
#define C_DIM 4
#define LIMIT_F 0.0766433975f                 // log(F32_MAX)/1024 - 0.01
#define N_OUT   (B_DIM * T_DIM * F_DIM * C_DIM)
#define L_CHUNK 64
#define N_CHUNK 8

__global__ __launch_bounds__(256, 7)
void outer_laplace_scan(const float* __restrict__ x,
                        const float* __restrict__ mem_r,
                        const float* __restrict__ mem_i,
                        const float* __restrict__ a,
                        const float* __restrict__ b,
                        float* __restrict__ out,
                        int mode, long long cap_f2)
{
    __shared__ float  xs[T_DIM * 8];          // x[b, :, f0:f0+8]  (16 KB)
    __shared__ float2 Ssm[N_CHUNK][32];       // chunk-local end sums (2 KB)

    const int tid   = threadIdx.x;
    const int lane  = tid & 31;               // (f_off, c) pair
    const int chunk = tid >> 5;               // warp id = chunk id

    const int bb    = blockIdx.x >> 7;        // batch
    const int f0    = (blockIdx.x & 127) << 3;
    const int f_off = lane >> 2;
    const int c     = lane & 3;
    const int f     = f0 + f_off;

    // ---- phase 0: stage x slice into smem (read-once -> evict-first) ----
    const float4* xg = (const float4*)(x + (size_t)bb * T_DIM * F_DIM + f0);
    #pragma unroll 4
    for (int idx = tid; idx < T_DIM * 2; idx += 256) {
        int t = idx >> 1, half = idx & 1;
        *(float4*)&xs[t * 8 + half * 4] = __ldcs(&xg[(size_t)t * (F_DIM / 4) + half]);
    }

    // ---- step coefficient w only (w^64 deferred past phase 1) ----
    const float ac = fminf(fmaxf(a[f], -LIMIT_F), -1e-8f);
    const float bc = b[c];
    {
    }
    float er = expf(ac);
    float sn, cs; sincosf(bc, &sn, &cs);
    const float wr = er * cs, wi = er * sn;

    __syncthreads();

    // ---- phase 1: chunk-local scan from zero ----
    {
        float yr = 0.f, yi = 0.f;
        const float* xp = &xs[chunk * L_CHUNK * 8 + f_off];
        #pragma unroll 16
        for (int k = 0; k < L_CHUNK; ++k) {
            float xv  = xp[k * 8];
            float nyr = fmaf(wr, yr, fmaf(-wi, yi, xv));
            float nyi = fmaf(wr, yi, wi * yr);
            yr = nyr; yi = nyi;
        }
        Ssm[chunk][lane] = make_float2(yr, yi);
    }
    __syncthreads();

    // ---- carry: E_{chunk-1} = Horner over previous chunk sums, seeded by mem ----
    float yr, yi;
    {
        float erL = expf(ac * (float)L_CHUNK);
        float snL, csL; sincosf(bc * (float)L_CHUNK, &snL, &csL);
        const float wLr = erL * csL, wLi = erL * snL;

        const int midx = (bb << 12) + (f << 2) + c;
        float cr = mem_r[midx], ci = mem_i[midx];
        for (int j = 0; j < chunk; ++j) {     // uniform per warp, <=7 iters
            float2 S = Ssm[j][lane];
            float nr = fmaf(wLr, cr, fmaf(-wLi, ci, S.x));
            float ni = fmaf(wLr, ci, fmaf(wLi, cr, S.y));
            cr = nr; ci = ni;
        }
        yr = cr; yi = ci;
    }

    // ---- phase 2: re-scan with correct init, streaming stores ----
    const float* xp = &xs[chunk * L_CHUNK * 8 + f_off];
    long long idx = ((long long)bb * T_DIM + chunk * L_CHUNK) * (F_DIM * C_DIM)
                  + (f << 2) + c;
    const int stride = F_DIM * C_DIM;

    if (mode == 0) {
        float2* ob = (float2*)out;
        #pragma unroll 16
        for (int k = 0; k < L_CHUNK; ++k) {
            float xv  = xp[k * 8];
            float nyr = fmaf(wr, yr, fmaf(-wi, yi, xv));
            float nyi = fmaf(wr, yi, wi * yr);
            yr = nyr; yi = nyi;
            __stcs(&ob[idx], make_float2(yr, yi));
            idx += stride;
        }
    } else if (mode == 1) {
        #pragma unroll 16
        for (int k = 0; k < L_CHUNK; ++k) {
            float xv  = xp[k * 8];
            float nyr = fmaf(wr, yr, fmaf(-wi, yi, xv));
            float nyi = fmaf(wr, yi, wi * yr);
            yr = nyr; yi = nyi;
            __stcs(&out[idx], yr);
            idx += stride;
        }
    } else {
        float2* ob = (float2*)out;
        #pragma unroll 8
        for (int k = 0; k < L_CHUNK; ++k) {
            float xv  = xp[k * 8];
            float nyr = fmaf(wr, yr, fmaf(-wi, yi, xv));
            float nyi = fmaf(wr, yi, wi * yr);
            yr = nyr; yi = nyi;
            if (idx < cap_f2) __stcs(&ob[idx], make_float2(yr, yi));
            idx += stride;
        }
    }
}

extern "C" void kernel_launch(void* const* d_in, const int* in_sizes, int n_in,
                              void* d_out, int out_size)
{
    const float* x     = nullptr;
    const float* mem_r = nullptr;
    const float* mem_i = nullptr;
    const float* a     = nullptr;
    const float* b     = nullptr;

    for (int i = 0; i < n_in; ++i) {
        switch (in_sizes[i]) {
            case B_DIM * T_DIM * F_DIM:
                x = (const float*)d_in[i]; break;
            case B_DIM * F_DIM * C_DIM:
                if (!mem_r) mem_r = (const float*)d_in[i];
                else        mem_i = (const float*)d_in[i];
                break;
            case F_DIM:
                a = (const float*)d_in[i]; break;
            case C_DIM:
                b = (const float*)d_in[i]; break;
            default: break;
        }
    }
    if (!x || !mem_r || !mem_i || !a || !b) {
        x     = (const float*)d_in[0];
        mem_r = (const float*)d_in[1];
        mem_i = (const float*)d_in[2];
        a     = (const float*)d_in[3];
        b     = (const float*)d_in[4];
    }

    int mode;
    long long cap_f2;
    if (out_size >= 2 * N_OUT)      { mode = 0; cap_f2 = N_OUT; }
    else if (out_size == N_OUT)     { mode = 1; cap_f2 = N_OUT; }
    else                            { mode = 2; cap_f2 = (long long)out_size / 2; }

    // 1024 blocks x 256 threads; 7 blocks/SM -> whole grid resident (1 wave).
    outer_laplace_scan<<<1024, 256>>>(x, mem_r, mem_i, a, b,
                                      (float*)d_out, mode, cap_f2);
}

// round 15
// speedup vs baseline: 1.0968x; 1.0968x over previous
#include <cuda_runtime.h>
#include <cuda_bf16.h>
#include <math.h>

// out[b,t,f,c] = sum_{s<=t} w^{t-s} x[b,s,f] + mem[b,f,c] * w^{t+1},
// w = exp(clip(a[f]) + i*b[c])  ==> complex IIR  y[t] = w*y[t-1] + x[t], y[-1]=mem.
// Parallel-in-T: 8 chunks of 64; chunk sums compose via E_i = w^64 E_{i-1} + S_i.
// FINAL (= R13, session best: bench 16.9us, ncu 17.2us):
//   R4 chunked-scan structure + __ldcs on x staging (read-once) and __stcs on
//   the output (write-streaming; 134MB cycles the 126MB L2 every launch).
// Session evidence says this sits at the L2-store path roofline (~150MB
// through LTS at ~8.7TB/s effective); all compute/occupancy levers were
// neutral or regressions.

#define B_DIM 8
#define T_DIM 512
#define F_DIM 1024
#define C_DIM 4
#define LIMIT_F 0.0766433975f                 // log(F32_MAX)/1024 - 0.01
#define N_OUT   (B_DIM * T_DIM * F_DIM * C_DIM)
#define L_CHUNK 64
#define N_CHUNK 8

__global__ __launch_bounds__(256, 6)
void outer_laplace_scan(const float* __restrict__ x,
                        const float* __restrict__ mem_r,
                        const float* __restrict__ mem_i,
                        const float* __restrict__ a,
                        const float* __restrict__ b,
                        float* __restrict__ out,
                        int mode, long long cap_f2)
{
    __shared__ float  xs[T_DIM * 8];          // x[b, :, f0:f0+8]  (16 KB)
    __shared__ float2 Ssm[N_CHUNK][32];       // chunk-local end sums (2 KB)

    const int tid   = threadIdx.x;
    const int lane  = tid & 31;               // (f_off, c) pair
    const int chunk = tid >> 5;               // warp id = chunk id

    const int bb    = blockIdx.x >> 7;        // batch
    const int f0    = (blockIdx.x & 127) << 3;
    const int f_off = lane >> 2;
    const int c     = lane & 3;
    const int f     = f0 + f_off;

    // ---- phase 0: stage x slice into smem (read-once -> evict-first) ----
    const float4* xg = (const float4*)(x + (size_t)bb * T_DIM * F_DIM + f0);
    #pragma unroll 4
    for (int idx = tid; idx < T_DIM * 2; idx += 256) {
        int t = idx >> 1, half = idx & 1;
        *(float4*)&xs[t * 8 + half * 4] = __ldcs(&xg[(size_t)t * (F_DIM / 4) + half]);
    }

    // ---- coefficients: w and w^64 (exact) ----
    float ac = fminf(fmaxf(a[f], -LIMIT_F), -1e-8f);
    float bc = b[c];
    float er = expf(ac);
    float sn, cs; sincosf(bc, &sn, &cs);
    const float wr = er * cs, wi = er * sn;

    float erL = expf(ac * (float)L_CHUNK);
    float snL, csL; sincosf(bc * (float)L_CHUNK, &snL, &csL);
    const float wLr = erL * csL, wLi = erL * snL;

    __syncthreads();

    // ---- phase 1: chunk-local scan from zero ----
    {
        float yr = 0.f, yi = 0.f;
        const float* xp = &xs[chunk * L_CHUNK * 8 + f_off];
        #pragma unroll 16
        for (int k = 0; k < L_CHUNK; ++k) {
            float xv  = xp[k * 8];
            float nyr = fmaf(wr, yr, fmaf(-wi, yi, xv));
            float nyi = fmaf(wr, yi, wi * yr);
            yr = nyr; yi = nyi;
        }
        Ssm[chunk][lane] = make_float2(yr, yi);
    }
    __syncthreads();

    // ---- carry: E_{chunk-1} = Horner over previous chunk sums, seeded by mem ----
    const int midx = (bb << 12) + (f << 2) + c;
    float cr = mem_r[midx], ci = mem_i[midx];
    for (int j = 0; j < chunk; ++j) {         // uniform per warp, <=7 iters
        float2 S = Ssm[j][lane];
        float nr = fmaf(wLr, cr, fmaf(-wLi, ci, S.x));
        float ni = fmaf(wLr, ci, fmaf(wLi, cr, S.y));
        cr = nr; ci = ni;
    }

    // ---- phase 2: re-scan with correct init, streaming stores ----
    float yr = cr, yi = ci;
    const float* xp = &xs[chunk * L_CHUNK * 8 + f_off];
    long long idx = ((long long)bb * T_DIM + chunk * L_CHUNK) * (F_DIM * C_DIM)
                  + (f << 2) + c;
    const int stride = F_DIM * C_DIM;

    if (mode == 0) {
        float2* ob = (float2*)out;
        #pragma unroll 16
        for (int k = 0; k < L_CHUNK; ++k) {
            float xv  = xp[k * 8];
            float nyr = fmaf(wr, yr, fmaf(-wi, yi, xv));
            float nyi = fmaf(wr, yi, wi * yr);
            yr = nyr; yi = nyi;
            __stcs(&ob[idx], make_float2(yr, yi));
            idx += stride;
        }
    } else if (mode == 1) {
        #pragma unroll 16
        for (int k = 0; k < L_CHUNK; ++k) {
            float xv  = xp[k * 8];
            float nyr = fmaf(wr, yr, fmaf(-wi, yi, xv));
            float nyi = fmaf(wr, yi, wi * yr);
            yr = nyr; yi = nyi;
            __stcs(&out[idx], yr);
            idx += stride;
        }
    } else {
        float2* ob = (float2*)out;
        #pragma unroll 8
        for (int k = 0; k < L_CHUNK; ++k) {
            float xv  = xp[k * 8];
            float nyr = fmaf(wr, yr, fmaf(-wi, yi, xv));
            float nyi = fmaf(wr, yi, wi * yr);
            yr = nyr; yi = nyi;
            if (idx < cap_f2) __stcs(&ob[idx], make_float2(yr, yi));
            idx += stride;
        }
    }
}

extern "C" void kernel_launch(void* const* d_in, const int* in_sizes, int n_in,
                              void* d_out, int out_size)
{
    const float* x     = nullptr;
    const float* mem_r = nullptr;
    const float* mem_i = nullptr;
    const float* a     = nullptr;
    const float* b     = nullptr;

    for (int i = 0; i < n_in; ++i) {
        switch (in_sizes[i]) {
            case B_DIM * T_DIM * F_DIM:
                x = (const float*)d_in[i]; break;
            case B_DIM * F_DIM * C_DIM:
                if (!mem_r) mem_r = (const float*)d_in[i];
                else        mem_i = (const float*)d_in[i];
                break;
            case F_DIM:
                a = (const float*)d_in[i]; break;
            case C_DIM:
                b = (const float*)d_in[i]; break;
            default: break;
        }
    }
    if (!x || !mem_r || !mem_i || !a || !b) {
        x     = (const float*)d_in[0];
        mem_r = (const float*)d_in[1];
        mem_i = (const float*)d_in[2];
        a     = (const float*)d_in[3];
        b     = (const float*)d_in[4];
    }

    int mode;
    long long cap_f2;
    if (out_size >= 2 * N_OUT)      { mode = 0; cap_f2 = N_OUT; }
    else if (out_size == N_OUT)     { mode = 1; cap_f2 = N_OUT; }
    else                            { mode = 2; cap_f2 = (long long)out_size / 2; }

    // 1024 blocks x 256 threads: block = (batch, 8 f-values), warps = chunks.
    outer_laplace_scan<<<1024, 256>>>(x, mem_r, mem_i, a, b,
                                      (float*)d_out, mode, cap_f2);
}